// round 3
// baseline (speedup 1.0000x reference)
#include <cuda_runtime.h>
#include <cuda_bf16.h>
#include <cstdint>

#define IMG_W 1536
#define IMG_H 1536
#define STRIDE 2
#define W_OUT (IMG_W / STRIDE)   // 768
#define H_OUT (IMG_H / STRIDE)   // 768
#define N_BOX 64

#define NBLK 192
#define ROWS_PB 4                 // 192 * 4 = 768 rows
#define NTHR 256                  // 3 columns per thread (768/256)

// Per-block partial max keys (order-preserving encoded conf). No pre-zero
// needed: every block writes all 64 slots every launch.
__device__ unsigned g_partial[NBLK * N_BOX];
__device__ int g_count = 0;       // reset to 0 by the last block (self-cleaning)

// Order-preserving encode of a float into unsigned; key(finite) > 0 always.
__device__ __forceinline__ unsigned enc(float f) {
    unsigned u = __float_as_uint(f);
    return (u & 0x80000000u) ? ~u : (u | 0x80000000u);
}
__device__ __forceinline__ float dec(unsigned k) {
    unsigned u = (k & 0x80000000u) ? (k & 0x7FFFFFFFu) : ~k;
    return __uint_as_float(u);
}

__global__ void __launch_bounds__(NTHR)
fused_kernel(const float* __restrict__ conf,
             const float* __restrict__ bboxes,
             float* __restrict__ out) {
    __shared__ float2 s_xb[N_BOX];          // (x1, x2), area_ok folded in
    __shared__ float2 s_yb[N_BOX];          // (y1, y2)
    __shared__ unsigned long long s_rowmask[ROWS_PB];
    __shared__ unsigned smax[N_BOX];
    __shared__ int s_last;

    const int tid = threadIdx.x;

    // ---- load boxes to smem (threads 0..63) ----
    if (tid < N_BOX) {
        float x1 = bboxes[tid * 5 + 0];
        float y1 = bboxes[tid * 5 + 1];
        float x2 = bboxes[tid * 5 + 2];
        float y2 = bboxes[tid * 5 + 3];
        bool ok = ((x2 - x1) * (y2 - y1)) != 0.0f;
        s_xb[tid] = ok ? make_float2(x1, x2) : make_float2(1e30f, -1e30f);
        s_yb[tid] = make_float2(y1, y2);
        smax[tid] = 0u;
    }
    __syncthreads();

    const int y0 = blockIdx.x * ROWS_PB;

    // ---- prefetch conf (12 independent loads; overlaps mask ALU below) ----
    float c[ROWS_PB][3];
    {
        const float* base = conf + (size_t)y0 * W_OUT + tid;
        #pragma unroll
        for (int r = 0; r < ROWS_PB; r++)
            #pragma unroll
            for (int i = 0; i < 3; i++)
                c[r][i] = __ldg(base + r * W_OUT + i * NTHR);
    }

    // ---- row masks (threads 0..3) ----
    if (tid < ROWS_PB) {
        float yc = (float)(y0 + tid) * 2.0f + 1.0f;
        unsigned long long m = 0ull;
        #pragma unroll 8
        for (int b = 0; b < N_BOX; b++) {
            float2 yb = s_yb[b];
            if (yc >= yb.x && yc <= yb.y) m |= (1ull << b);
        }
        s_rowmask[tid] = m;
    }

    // ---- column masks for this thread's 3 columns (registers) ----
    unsigned long long cm[3];
    #pragma unroll
    for (int i = 0; i < 3; i++) {
        float xc = (float)(tid + i * NTHR) * 2.0f + 1.0f;
        unsigned long long m = 0ull;
        #pragma unroll 8
        for (int b = 0; b < N_BOX; b++) {
            float2 xb = s_xb[b];
            if (xc >= xb.x && xc <= xb.y) m |= (1ull << b);
        }
        cm[i] = m;
    }
    __syncthreads();

    // ---- pixel tests ----
    #pragma unroll
    for (int r = 0; r < ROWS_PB; r++) {
        unsigned long long rm = s_rowmask[r];
        if (rm == 0ull) continue;            // uniform branch
        #pragma unroll
        for (int i = 0; i < 3; i++) {
            unsigned long long m = rm & cm[i];
            if (m != 0ull && (m & (m - 1ull)) == 0ull) {  // exactly one box
                int b = __ffsll((long long)m) - 1;
                atomicMax(&smax[b], enc(c[r][i]));
            }
        }
    }
    __syncthreads();

    // ---- publish partial; last block reduces & writes d_out ----
    if (tid < N_BOX) g_partial[blockIdx.x * N_BOX + tid] = smax[tid];
    __threadfence();
    if (tid == 0) {
        int prev = atomicAdd(&g_count, 1);
        s_last = (prev == NBLK - 1) ? 1 : 0;
    }
    __syncthreads();

    if (s_last) {
        __threadfence();                     // acquire published partials
        int b  = tid & (N_BOX - 1);
        int ch = tid >> 6;                   // 4 chunks of 48 blocks
        unsigned k = 0u;
        for (int j = ch; j < NBLK; j += 4)
            k = max(k, g_partial[j * N_BOX + b]);
        atomicMax(&smax[b], k);              // smax holds own partial; max idempotent
        __syncthreads();
        if (tid < N_BOX) {
            unsigned kk = smax[tid];
            float s = 0.0f, v = 0.0f;
            if (kk != 0u) {
                float f = dec(kk);
                s = 1.0f / (1.0f + __expf(-f));
                v = 1.0f;
            }
            out[tid] = s;                    // writes ALL 128 outputs
            out[N_BOX + tid] = v;
        }
        if (tid == 0) g_count = 0;           // reset for next replay
    }
}

extern "C" void kernel_launch(void* const* d_in, const int* in_sizes, int n_in,
                              void* d_out, int out_size) {
    const float* conf   = (const float*)d_in[0];  // (1,1,768,768) f32
    const float* bboxes = (const float*)d_in[2];  // (64,5) f32
    float* out = (float*)d_out;                   // scores[64] ++ valid[64]

    fused_kernel<<<NBLK, NTHR>>>(conf, bboxes, out);
}

// round 4
// speedup vs baseline: 1.8125x; 1.8125x over previous
#include <cuda_runtime.h>
#include <cuda_bf16.h>
#include <cstdint>

#define IMG_W 1536
#define IMG_H 1536
#define STRIDE 2
#define W_OUT (IMG_W / STRIDE)   // 768
#define H_OUT (IMG_H / STRIDE)   // 768
#define N_BOX 64

#define TBX 64                   // tile cols
#define TBY 32                   // tile rows
#define GX  (W_OUT / TBX)        // 12
#define GY  (H_OUT / TBY)        // 24
#define NBLK (GX * GY)           // 288
#define NTHR 256

// Per-block partial max keys. Every block writes all 64 slots each launch.
__device__ unsigned g_partial[NBLK * N_BOX];
__device__ int g_count = 0;      // reset by the last block (self-cleaning)

// Order-preserving encode of float -> unsigned; key(finite) > 0 always.
__device__ __forceinline__ unsigned enc(float f) {
    unsigned u = __float_as_uint(f);
    return (u & 0x80000000u) ? ~u : (u | 0x80000000u);
}
__device__ __forceinline__ float dec(unsigned k) {
    unsigned u = (k & 0x80000000u) ? (k & 0x7FFFFFFFu) : ~k;
    return __uint_as_float(u);
}

__global__ void __launch_bounds__(NTHR)
fused_kernel(const float* __restrict__ conf,
             const float* __restrict__ bboxes,
             float* __restrict__ out) {
    __shared__ __align__(16) unsigned long long s_cm[TBX];  // col masks
    __shared__ unsigned long long s_rm[TBY];                // row masks
    __shared__ unsigned smax[N_BOX];
    __shared__ int s_last;

    const int tid  = threadIdx.x;
    const int warp = tid >> 5;
    const int lane = tid & 31;
    const int pair = warp >> 1;        // 0..3
    const int half = warp & 1;         // 0: boxes 0-31, 1: boxes 32-63

    if (tid < N_BOX) smax[tid] = 0u;

    // This lane's box (per warp-half). Scalar loads; L2-hot after first tiles.
    const int box = (half << 5) | lane;
    const float x1 = __ldg(bboxes + box * 5 + 0);
    const float y1 = __ldg(bboxes + box * 5 + 1);
    const float x2 = __ldg(bboxes + box * 5 + 2);
    const float y2 = __ldg(bboxes + box * 5 + 3);
    const bool ok  = ((x2 - x1) * (y2 - y1)) != 0.0f;

    const int col0 = blockIdx.x * TBX;
    const int row0 = blockIdx.y * TBY;

    // ---- ballot-built masks: 1 ballot = 32 bits of one column/row mask ----
    unsigned* s_cm32 = (unsigned*)s_cm;
    unsigned* s_rm32 = (unsigned*)s_rm;
    #pragma unroll
    for (int i = 0; i < TBX / 4; i++) {          // 16 cols per warp-pair
        int c = pair * (TBX / 4) + i;
        float xc = (float)(col0 + c) * 2.0f + 1.0f;
        bool in = ok && (xc >= x1) && (xc <= x2);
        unsigned bal = __ballot_sync(0xFFFFFFFFu, in);
        if (lane == 0) s_cm32[c * 2 + half] = bal;
    }
    #pragma unroll
    for (int i = 0; i < TBY / 4; i++) {          // 8 rows per warp-pair
        int r = pair * (TBY / 4) + i;
        float yc = (float)(row0 + r) * 2.0f + 1.0f;
        bool in = (yc >= y1) && (yc <= y2);
        unsigned bal = __ballot_sync(0xFFFFFFFFu, in);
        if (lane == 0) s_rm32[r * 2 + half] = bal;
    }
    __syncthreads();

    // ---- pixel phase: thread -> 4 cols (float4) x 2 rows ----
    const int xq = tid & 15;                     // float4 index within tile
    const int r0 = tid >> 4;                     // 0..15; rows r0, r0+16

    const ulonglong2 A = *reinterpret_cast<const ulonglong2*>(s_cm + xq * 4);
    const ulonglong2 B = *reinterpret_cast<const ulonglong2*>(s_cm + xq * 4 + 2);
    const unsigned long long rm0 = s_rm[r0];
    const unsigned long long rm1 = s_rm[r0 + 16];

    const unsigned long long anym = (rm0 | rm1) & (A.x | A.y | B.x | B.y);
    if (__any_sync(0xFFFFFFFFu, anym != 0ull)) {
        const float* p = conf + (size_t)(row0 + r0) * W_OUT + col0 + xq * 4;
        const float4 c0 = *reinterpret_cast<const float4*>(p);
        const float4 c1 = *reinterpret_cast<const float4*>(p + 16 * W_OUT);

        const unsigned long long cms[4] = { A.x, A.y, B.x, B.y };
        const float cv0[4] = { c0.x, c0.y, c0.z, c0.w };
        const float cv1[4] = { c1.x, c1.y, c1.z, c1.w };

        #pragma unroll
        for (int i = 0; i < 4; i++) {
            unsigned long long m0 = rm0 & cms[i];
            if (m0 != 0ull && (m0 & (m0 - 1ull)) == 0ull) {
                int b = __ffsll((long long)m0) - 1;
                atomicMax(&smax[b], enc(cv0[i]));
            }
            unsigned long long m1 = rm1 & cms[i];
            if (m1 != 0ull && (m1 & (m1 - 1ull)) == 0ull) {
                int b = __ffsll((long long)m1) - 1;
                atomicMax(&smax[b], enc(cv1[i]));
            }
        }
    }
    __syncthreads();

    // ---- publish partial; last block reduces & writes d_out ----
    const int bid = blockIdx.y * GX + blockIdx.x;
    if (tid < N_BOX) g_partial[bid * N_BOX + tid] = smax[tid];
    __threadfence();
    if (tid == 0) {
        int prev = atomicAdd(&g_count, 1);
        s_last = (prev == NBLK - 1) ? 1 : 0;
    }
    __syncthreads();

    if (s_last) {
        __threadfence();
        int b  = tid & (N_BOX - 1);
        int ch = tid >> 6;                       // 4 chunks of 72 blocks
        unsigned k = 0u;
        #pragma unroll 4
        for (int j = ch; j < NBLK; j += 4)
            k = max(k, g_partial[j * N_BOX + b]);
        atomicMax(&smax[b], k);
        __syncthreads();
        if (tid < N_BOX) {
            unsigned kk = smax[tid];
            float s = 0.0f, v = 0.0f;
            if (kk != 0u) {
                float f = dec(kk);
                s = 1.0f / (1.0f + __expf(-f));
                v = 1.0f;
            }
            out[tid] = s;
            out[N_BOX + tid] = v;
        }
        if (tid == 0) g_count = 0;               // reset for next replay
    }
}

extern "C" void kernel_launch(void* const* d_in, const int* in_sizes, int n_in,
                              void* d_out, int out_size) {
    const float* conf   = (const float*)d_in[0];  // (1,1,768,768) f32
    const float* bboxes = (const float*)d_in[2];  // (64,5) f32
    float* out = (float*)d_out;                   // scores[64] ++ valid[64]

    dim3 grid(GX, GY);
    fused_kernel<<<grid, NTHR>>>(conf, bboxes, out);
}

// round 5
// speedup vs baseline: 2.6557x; 1.4652x over previous
#include <cuda_runtime.h>
#include <cuda_bf16.h>
#include <cstdint>

#define IMG_W 1536
#define IMG_H 1536
#define STRIDE 2
#define W_OUT (IMG_W / STRIDE)   // 768
#define H_OUT (IMG_H / STRIDE)   // 768
#define N_BOX 64

#define TBX 64                   // tile cols
#define TBY 16                   // tile rows
#define GX  (W_OUT / TBX)        // 12
#define GY  (H_OUT / TBY)        // 48
#define NBLK (GX * GY)           // 576
#define NTHR 256                 // 1 float4 (4 cols) x 1 row per thread

// Global accumulator: rest state is all-zero (zero-init at module load; the
// last block resets it after consuming). Keys of finite floats are > 0.
__device__ unsigned g_accum[N_BOX];
__device__ int g_count = 0;

// Order-preserving encode of float -> unsigned; key(finite) > 0 always.
__device__ __forceinline__ unsigned enc(float f) {
    unsigned u = __float_as_uint(f);
    return (u & 0x80000000u) ? ~u : (u | 0x80000000u);
}
__device__ __forceinline__ float dec(unsigned k) {
    unsigned u = (k & 0x80000000u) ? (k & 0x7FFFFFFFu) : ~k;
    return __uint_as_float(u);
}

__global__ void __launch_bounds__(NTHR)
fused_kernel(const float* __restrict__ conf,
             const float* __restrict__ bboxes,
             float* __restrict__ out) {
    __shared__ __align__(16) unsigned long long s_cm[TBX];  // col masks
    __shared__ unsigned long long s_rm[TBY];                // row masks
    __shared__ unsigned smax[N_BOX];
    __shared__ int s_last;

    const int tid  = threadIdx.x;
    const int warp = tid >> 5;
    const int lane = tid & 31;
    const int pair = warp >> 1;        // 0..3
    const int half = warp & 1;         // 0: boxes 0-31, 1: boxes 32-63

    if (tid < N_BOX) smax[tid] = 0u;

    // This lane's box (per warp-half).
    const int box = (half << 5) | lane;
    const float x1 = __ldg(bboxes + box * 5 + 0);
    const float y1 = __ldg(bboxes + box * 5 + 1);
    const float x2 = __ldg(bboxes + box * 5 + 2);
    const float y2 = __ldg(bboxes + box * 5 + 3);
    const bool ok  = ((x2 - x1) * (y2 - y1)) != 0.0f;

    const int col0 = blockIdx.x * TBX;
    const int row0 = blockIdx.y * TBY;

    // ---- ballot-built masks: 1 ballot = 32 bits of one column/row mask ----
    unsigned* s_cm32 = (unsigned*)s_cm;
    unsigned* s_rm32 = (unsigned*)s_rm;
    #pragma unroll
    for (int i = 0; i < TBX / 4; i++) {          // 16 cols per warp-pair
        int c = pair * (TBX / 4) + i;
        float xc = (float)(col0 + c) * 2.0f + 1.0f;
        bool in = ok && (xc >= x1) && (xc <= x2);
        unsigned bal = __ballot_sync(0xFFFFFFFFu, in);
        if (lane == 0) s_cm32[c * 2 + half] = bal;
    }
    #pragma unroll
    for (int i = 0; i < TBY / 4; i++) {          // 4 rows per warp-pair
        int r = pair * (TBY / 4) + i;
        float yc = (float)(row0 + r) * 2.0f + 1.0f;
        bool in = (yc >= y1) && (yc <= y2);
        unsigned bal = __ballot_sync(0xFFFFFFFFu, in);
        if (lane == 0) s_rm32[r * 2 + half] = bal;
    }
    __syncthreads();

    // ---- pixel phase: thread -> one float4 (4 cols) in one row ----
    const int xq = tid & 15;                     // float4 index within tile
    const int r  = tid >> 4;                     // 0..15

    const ulonglong2 A = *reinterpret_cast<const ulonglong2*>(s_cm + xq * 4);
    const ulonglong2 B = *reinterpret_cast<const ulonglong2*>(s_cm + xq * 4 + 2);
    const unsigned long long rm = s_rm[r];

    const unsigned long long anym = rm & (A.x | A.y | B.x | B.y);
    bool block_has_work = true;
    if (__any_sync(0xFFFFFFFFu, anym != 0ull)) {
        const float4 c4 = *reinterpret_cast<const float4*>(
            conf + (size_t)(row0 + r) * W_OUT + col0 + xq * 4);
        const unsigned long long cms[4] = { A.x, A.y, B.x, B.y };
        const float cv[4] = { c4.x, c4.y, c4.z, c4.w };
        #pragma unroll
        for (int i = 0; i < 4; i++) {
            unsigned long long m = rm & cms[i];
            if (m != 0ull && (m & (m - 1ull)) == 0ull) {  // exactly one box
                int b = __ffsll((long long)m) - 1;
                atomicMax(&smax[b], enc(cv[i]));
            }
        }
    }
    __syncthreads();

    // ---- publish: direct global atomicMax (skip zero slots) ----
    if (tid < N_BOX) {
        unsigned k = smax[tid];
        if (k != 0u) atomicMax(&g_accum[tid], k);
    }
    __syncthreads();
    if (tid == 0) {
        __threadfence();                          // release (1 thread only)
        int prev = atomicAdd(&g_count, 1);
        s_last = (prev == NBLK - 1) ? 1 : 0;
    }
    __syncthreads();

    // ---- last block: consume, write outputs, reset state ----
    if (s_last) {
        if (tid == 0) __threadfence();            // acquire
        __syncthreads();
        if (tid < N_BOX) {
            // atomic read: coherent view of L2 state, and leaves value intact
            unsigned kk = atomicMax(&g_accum[tid], 0u);
            float s = 0.0f, v = 0.0f;
            if (kk != 0u) {
                float f = dec(kk);
                s = 1.0f / (1.0f + __expf(-f));
                v = 1.0f;
            }
            out[tid] = s;
            out[N_BOX + tid] = v;
            g_accum[tid] = 0u;                    // reset for next replay
        }
        if (tid == 0) g_count = 0;                // reset for next replay
    }
}

extern "C" void kernel_launch(void* const* d_in, const int* in_sizes, int n_in,
                              void* d_out, int out_size) {
    const float* conf   = (const float*)d_in[0];  // (1,1,768,768) f32
    const float* bboxes = (const float*)d_in[2];  // (64,5) f32
    float* out = (float*)d_out;                   // scores[64] ++ valid[64]

    dim3 grid(GX, GY);
    fused_kernel<<<grid, NTHR>>>(conf, bboxes, out);
}